// round 4
// baseline (speedup 1.0000x reference)
#include <cuda_runtime.h>
#include <cstdint>

#define N_PAIRS 500000
#define LMAX    4
#define NM      16
#define HID     32
#define NSPEC   4
#define PAD     64                    // bucket alignment (warp owns 64-entry chunk)
#define NSORT   (N_PAIRS + NSPEC * PAD)

// Scratch (allocation-free rule: __device__ globals)
__device__ int d_count[NSPEC];
__device__ int d_cursor[NSPEC];
__device__ int d_aoff[NSPEC + 1];     // padded (64-aligned) bucket offsets
__device__ int d_sorted[NSORT];
__device__ int d_stride;              // 1 = species int32, 2 = int64 (read low words)

// ---------------- dtype detection + init ----------------

__global__ void k_init(const int* __restrict__ sp32) {
    __shared__ int any_nonzero;
    int t = threadIdx.x;
    if (t == 0) any_nonzero = 0;
    if (t < NSPEC) d_count[t] = 0;
    __syncthreads();
    if (sp32[2 * t + 1] != 0) atomicOr(&any_nonzero, 1);
    __syncthreads();
    if (t == 0) d_stride = any_nonzero ? 1 : 2;
}

// ---------------- sort-by-species pipeline ----------------

__global__ void k_hist(const int* __restrict__ sp32) {
    __shared__ int cnt[NSPEC];
    int tid = threadIdx.x;
    if (tid < NSPEC) cnt[tid] = 0;
    __syncthreads();
    const int stride = d_stride;
    int i = blockIdx.x * blockDim.x + tid;
    if (i < N_PAIRS) {
        int sp = sp32[i * stride] & 3;
        atomicAdd(&cnt[sp], 1);
    }
    __syncthreads();
    if (tid < NSPEC && cnt[tid] > 0) atomicAdd(&d_count[tid], cnt[tid]);
}

__global__ void k_offsets() {
    int acc = 0;
    for (int s = 0; s < NSPEC; ++s) {
        d_aoff[s] = acc;
        d_cursor[s] = acc;
        acc += (d_count[s] + PAD - 1) & ~(PAD - 1);   // pad each bucket to 64
    }
    d_aoff[NSPEC] = acc;
}

__global__ void k_scatter(const int* __restrict__ sp32) {
    __shared__ int cnt[NSPEC];
    __shared__ int base[NSPEC];
    int tid = threadIdx.x;
    if (tid < NSPEC) cnt[tid] = 0;
    __syncthreads();
    const int stride = d_stride;
    int i = blockIdx.x * blockDim.x + tid;
    int sp = 0;
    if (i < N_PAIRS) {
        sp = sp32[i * stride] & 3;
        atomicAdd(&cnt[sp], 1);
    }
    __syncthreads();
    if (tid < NSPEC) {
        base[tid] = (cnt[tid] > 0) ? atomicAdd(&d_cursor[tid], cnt[tid]) : 0;
        cnt[tid] = 0;   // reuse as local rank cursor
    }
    __syncthreads();
    if (i < N_PAIRS) {
        int r = atomicAdd(&cnt[sp], 1);
        d_sorted[base[sp] + r] = i;
    }
}

// Fill the pad tail of each bucket with a duplicate of the bucket's first index.
// Duplicates recompute & rewrite identical output values — deterministic & benign.
__global__ void k_pad() {
    int s = blockIdx.x;                       // 4 blocks, 64 threads
    int start = d_aoff[s] + d_count[s];
    int end   = d_aoff[s + 1];
    int t = threadIdx.x;
    if (start + t < end) d_sorted[start + t] = d_sorted[d_aoff[s]];
}

// ---------------- packed f32x2 helpers ----------------

__device__ __forceinline__ uint64_t pack2(float v) {
    uint64_t r;
    unsigned u = __float_as_uint(v);
    asm("mov.b64 %0, {%1, %1};" : "=l"(r) : "r"(u));
    return r;
}

__device__ __forceinline__ void unpack2(uint64_t p, float& a, float& b) {
    unsigned lo, hi;
    asm("mov.b64 {%0, %1}, %2;" : "=r"(lo), "=r"(hi) : "l"(p));
    a = __uint_as_float(lo);
    b = __uint_as_float(hi);
}

__device__ __forceinline__ void fma2(uint64_t& d, uint64_t a, uint64_t b) {
    asm("fma.rn.f32x2 %0, %1, %2, %0;" : "+l"(d) : "l"(a), "l"(b));
}

__device__ __forceinline__ float silu(float v) {
    return __fdividef(v, 1.0f + __expf(-v));
}

// ---------------- main MLP kernel ----------------

// Dual-pair fused dense layer: one LDS.128 weight fetch feeds 4 FFMA2
// (2 per pair). W row-major [IN][OUT] in smem, warp-uniform address.
template <int IN, int OUT, bool ACT>
__device__ __forceinline__ void layer2d(const float* __restrict__ w,
                                        const float* __restrict__ in0,
                                        const float* __restrict__ in1,
                                        float* __restrict__ out0,
                                        float* __restrict__ out1) {
    uint64_t acc0[OUT / 2], acc1[OUT / 2];
#pragma unroll
    for (int o = 0; o < OUT / 2; ++o) { acc0[o] = 0ull; acc1[o] = 0ull; }

#pragma unroll
    for (int i = 0; i < IN; ++i) {
        const uint64_t dup0 = pack2(in0[i]);
        const uint64_t dup1 = pack2(in1[i]);
        const ulonglong2* wrow = reinterpret_cast<const ulonglong2*>(w + i * OUT);
#pragma unroll
        for (int o4 = 0; o4 < OUT / 4; ++o4) {
            ulonglong2 wv = wrow[o4];           // LDS.128 broadcast, shared by both pairs
            fma2(acc0[o4 * 2 + 0], dup0, wv.x);
            fma2(acc0[o4 * 2 + 1], dup0, wv.y);
            fma2(acc1[o4 * 2 + 0], dup1, wv.x);
            fma2(acc1[o4 * 2 + 1], dup1, wv.y);
        }
    }

#pragma unroll
    for (int o2 = 0; o2 < OUT / 2; ++o2) {
        float v0, v1, u0, u1;
        unpack2(acc0[o2], v0, v1);
        unpack2(acc1[o2], u0, u1);
        if (ACT) { v0 = silu(v0); v1 = silu(v1); u0 = silu(u0); u1 = silu(u1); }
        out0[o2 * 2 + 0] = v0; out0[o2 * 2 + 1] = v1;
        out1[o2 * 2 + 0] = u0; out1[o2 * 2 + 1] = u1;
    }
}

// Per-species smem weight block layout (3072 floats):
// [0,512) W1 (16x32), [512,1536) W2 (32x32), [1536,2560) W3 (32x32), [2560,3072) W4 (32x16)
#define SPBLK 3072

__global__ void __launch_bounds__(128)
k_mlp(const float* __restrict__ xg,
      const float* __restrict__ W1, const float* __restrict__ W2,
      const float* __restrict__ W3, const float* __restrict__ W4,
      float* __restrict__ out) {
    const int l = blockIdx.y;
    __shared__ float wsm[NSPEC * SPBLK];   // 48 KB

    for (int t = threadIdx.x; t < NSPEC * SPBLK; t += blockDim.x) {
        int s = t / SPBLK;
        int j = t - s * SPBLK;
        float v;
        if (j < 512)        v = W1[(l * NSPEC + s) * 512  + j];
        else if (j < 1536)  v = W2[(l * NSPEC + s) * 1024 + (j - 512)];
        else if (j < 2560)  v = W3[(l * NSPEC + s) * 1024 + (j - 1536)];
        else                v = W4[(l * NSPEC + s) * 512  + (j - 2560)];
        wsm[t] = v;
    }
    __syncthreads();

    const int aoff1 = d_aoff[1], aoff2 = d_aoff[2], aoff3 = d_aoff[3];
    const int nchunk = d_aoff[NSPEC] / PAD;   // 64-entry warp chunks, bucket-pure

    const int lane = threadIdx.x & 31;
    const int wid  = threadIdx.x >> 5;

    for (int c = blockIdx.x * 4 + wid; c < nchunk; c += gridDim.x * 4) {
        const int pbase = c * PAD;
        // species uniform across the whole 64-entry chunk (buckets 64-aligned)
        const int sp = (pbase >= aoff2) ? ((pbase >= aoff3) ? 3 : 2)
                                        : ((pbase >= aoff1) ? 1 : 0);
        const float* w = &wsm[sp * SPBLK];

        const int idx0 = d_sorted[pbase + lane];
        const int idx1 = d_sorted[pbase + lane + 32];

        float a0[HID], b0[HID], a1[HID], b1[HID];

        const float4* x0 = reinterpret_cast<const float4*>(xg + ((size_t)idx0 * LMAX + l) * NM);
        const float4* x1 = reinterpret_cast<const float4*>(xg + ((size_t)idx1 * LMAX + l) * NM);
#pragma unroll
        for (int q = 0; q < 4; ++q) {
            float4 v0 = x0[q], v1 = x1[q];
            a0[q * 4 + 0] = v0.x; a0[q * 4 + 1] = v0.y; a0[q * 4 + 2] = v0.z; a0[q * 4 + 3] = v0.w;
            a1[q * 4 + 0] = v1.x; a1[q * 4 + 1] = v1.y; a1[q * 4 + 2] = v1.z; a1[q * 4 + 3] = v1.w;
        }

        layer2d<NM,  HID, true >(w,        a0, a1, b0, b1);   // L1 + silu
        layer2d<HID, HID, true >(w + 512,  b0, b1, a0, a1);   // L2 + silu
        layer2d<HID, HID, true >(w + 1536, a0, a1, b0, b1);   // L3 + silu
        layer2d<HID, NM,  false>(w + 2560, b0, b1, a0, a1);   // L4

        float4* o0 = reinterpret_cast<float4*>(out + ((size_t)idx0 * LMAX + l) * NM);
        float4* o1 = reinterpret_cast<float4*>(out + ((size_t)idx1 * LMAX + l) * NM);
#pragma unroll
        for (int q = 0; q < 4; ++q) {
            o0[q] = make_float4(a0[q * 4 + 0], a0[q * 4 + 1], a0[q * 4 + 2], a0[q * 4 + 3]);
            o1[q] = make_float4(a1[q * 4 + 0], a1[q * 4 + 1], a1[q * 4 + 2], a1[q * 4 + 3]);
        }
    }
}

// ---------------- launch ----------------

extern "C" void kernel_launch(void* const* d_in, const int* in_sizes, int n_in,
                              void* d_out, int out_size) {
    const float* x   = (const float*)d_in[0];
    const int*   sp  = (const int*)d_in[1];   // int32 or int64 — detected on device
    const float* W1  = (const float*)d_in[2];
    const float* W2  = (const float*)d_in[3];
    const float* W3  = (const float*)d_in[4];
    const float* W4  = (const float*)d_in[5];
    float*       out = (float*)d_out;

    const int nblk = (N_PAIRS + 255) / 256;

    k_init<<<1, 256>>>(sp);
    k_hist<<<nblk, 256>>>(sp);
    k_offsets<<<1, 1>>>();
    k_scatter<<<nblk, 256>>>(sp);
    k_pad<<<NSPEC, PAD>>>();

    dim3 grid(304, LMAX);   // 4 warps/CTA, grid-stride over 64-entry chunks
    k_mlp<<<grid, 128>>>(x, W1, W2, W3, W4, out);
}

// round 5
// speedup vs baseline: 1.0375x; 1.0375x over previous
#include <cuda_runtime.h>
#include <cstdint>

#define N_PAIRS 500000
#define LMAX    4
#define NM      16
#define HID     32
#define NSPEC   4
#define PAD     64                    // bucket alignment (warp owns 64-entry chunk)
#define NSORT   (N_PAIRS + NSPEC * PAD)

// Scratch (allocation-free rule: __device__ globals)
__device__ int d_count[NSPEC];
__device__ int d_cursor[NSPEC];
__device__ int d_aoff[NSPEC + 1];     // padded (64-aligned) bucket offsets
__device__ int d_sorted[NSORT];
__device__ int d_stride;              // 1 = species int32, 2 = int64 (read low words)

// ---------------- dtype detection + init ----------------

__global__ void k_init(const int* __restrict__ sp32) {
    __shared__ int any_nonzero;
    int t = threadIdx.x;
    if (t == 0) any_nonzero = 0;
    if (t < NSPEC) d_count[t] = 0;
    __syncthreads();
    if (sp32[2 * t + 1] != 0) atomicOr(&any_nonzero, 1);
    __syncthreads();
    if (t == 0) d_stride = any_nonzero ? 1 : 2;
}

// ---------------- sort-by-species pipeline ----------------

__global__ void k_hist(const int* __restrict__ sp32) {
    __shared__ int cnt[NSPEC];
    int tid = threadIdx.x;
    if (tid < NSPEC) cnt[tid] = 0;
    __syncthreads();
    const int stride = d_stride;
    int i = blockIdx.x * blockDim.x + tid;
    if (i < N_PAIRS) {
        int sp = sp32[i * stride] & 3;
        atomicAdd(&cnt[sp], 1);
    }
    __syncthreads();
    if (tid < NSPEC && cnt[tid] > 0) atomicAdd(&d_count[tid], cnt[tid]);
}

__global__ void k_offsets() {
    int acc = 0;
    for (int s = 0; s < NSPEC; ++s) {
        d_aoff[s] = acc;
        d_cursor[s] = acc;
        acc += (d_count[s] + PAD - 1) & ~(PAD - 1);   // pad each bucket to 64
    }
    d_aoff[NSPEC] = acc;
}

__global__ void k_scatter(const int* __restrict__ sp32) {
    __shared__ int cnt[NSPEC];
    __shared__ int base[NSPEC];
    int tid = threadIdx.x;
    if (tid < NSPEC) cnt[tid] = 0;
    __syncthreads();
    const int stride = d_stride;
    int i = blockIdx.x * blockDim.x + tid;
    int sp = 0;
    if (i < N_PAIRS) {
        sp = sp32[i * stride] & 3;
        atomicAdd(&cnt[sp], 1);
    }
    __syncthreads();
    if (tid < NSPEC) {
        base[tid] = (cnt[tid] > 0) ? atomicAdd(&d_cursor[tid], cnt[tid]) : 0;
        cnt[tid] = 0;   // reuse as local rank cursor
    }
    __syncthreads();
    if (i < N_PAIRS) {
        int r = atomicAdd(&cnt[sp], 1);
        d_sorted[base[sp] + r] = i;
    }
}

// Fill the pad tail of each bucket with a duplicate of the bucket's first index.
// Duplicates recompute & rewrite identical output values — deterministic & benign.
__global__ void k_pad() {
    int s = blockIdx.x;                       // 4 blocks, 64 threads
    int start = d_aoff[s] + d_count[s];
    int end   = d_aoff[s + 1];
    int t = threadIdx.x;
    if (start + t < end) d_sorted[start + t] = d_sorted[d_aoff[s]];
}

// ---------------- packed f32x2 helpers ----------------

__device__ __forceinline__ uint64_t pack2(float v) {
    uint64_t r;
    unsigned u = __float_as_uint(v);
    asm("mov.b64 %0, {%1, %1};" : "=l"(r) : "r"(u));
    return r;
}

__device__ __forceinline__ void unpack2(uint64_t p, float& a, float& b) {
    unsigned lo, hi;
    asm("mov.b64 {%0, %1}, %2;" : "=r"(lo), "=r"(hi) : "l"(p));
    a = __uint_as_float(lo);
    b = __uint_as_float(hi);
}

__device__ __forceinline__ void fma2(uint64_t& d, uint64_t a, uint64_t b) {
    asm("fma.rn.f32x2 %0, %1, %2, %0;" : "+l"(d) : "l"(a), "l"(b));
}

__device__ __forceinline__ float silu(float v) {
    return __fdividef(v, 1.0f + __expf(-v));
}

// ---------------- main MLP kernel ----------------

// Dual-pair fused dense layer: one LDS.128 weight fetch feeds 4 FFMA2
// (2 per pair). W row-major [IN][OUT] in smem, warp-uniform address.
template <int IN, int OUT, bool ACT>
__device__ __forceinline__ void layer2d(const float* __restrict__ w,
                                        const float* __restrict__ in0,
                                        const float* __restrict__ in1,
                                        float* __restrict__ out0,
                                        float* __restrict__ out1) {
    uint64_t acc0[OUT / 2], acc1[OUT / 2];
#pragma unroll
    for (int o = 0; o < OUT / 2; ++o) { acc0[o] = 0ull; acc1[o] = 0ull; }

#pragma unroll
    for (int i = 0; i < IN; ++i) {
        const uint64_t dup0 = pack2(in0[i]);
        const uint64_t dup1 = pack2(in1[i]);
        const ulonglong2* wrow = reinterpret_cast<const ulonglong2*>(w + i * OUT);
#pragma unroll
        for (int o4 = 0; o4 < OUT / 4; ++o4) {
            ulonglong2 wv = wrow[o4];           // LDS.128 broadcast, shared by both pairs
            fma2(acc0[o4 * 2 + 0], dup0, wv.x);
            fma2(acc0[o4 * 2 + 1], dup0, wv.y);
            fma2(acc1[o4 * 2 + 0], dup1, wv.x);
            fma2(acc1[o4 * 2 + 1], dup1, wv.y);
        }
    }

#pragma unroll
    for (int o2 = 0; o2 < OUT / 2; ++o2) {
        float v0, v1, u0, u1;
        unpack2(acc0[o2], v0, v1);
        unpack2(acc1[o2], u0, u1);
        if (ACT) { v0 = silu(v0); v1 = silu(v1); u0 = silu(u0); u1 = silu(u1); }
        out0[o2 * 2 + 0] = v0; out0[o2 * 2 + 1] = v1;
        out1[o2 * 2 + 0] = u0; out1[o2 * 2 + 1] = u1;
    }
}

// Per-species smem weight block layout (3072 floats):
// [0,512) W1 (16x32), [512,1536) W2 (32x32), [1536,2560) W3 (32x32), [2560,3072) W4 (32x16)
#define SPBLK 3072

__global__ void __launch_bounds__(128, 3)   // cap ~170 regs -> 3 CTAs = 12 warps/SM
k_mlp(const float* __restrict__ xg,
      const float* __restrict__ W1, const float* __restrict__ W2,
      const float* __restrict__ W3, const float* __restrict__ W4,
      float* __restrict__ out) {
    const int l = blockIdx.y;
    __shared__ float wsm[NSPEC * SPBLK];   // 48 KB (x3 CTAs = 144 KB/SM)

    for (int t = threadIdx.x; t < NSPEC * SPBLK; t += blockDim.x) {
        int s = t / SPBLK;
        int j = t - s * SPBLK;
        float v;
        if (j < 512)        v = W1[(l * NSPEC + s) * 512  + j];
        else if (j < 1536)  v = W2[(l * NSPEC + s) * 1024 + (j - 512)];
        else if (j < 2560)  v = W3[(l * NSPEC + s) * 1024 + (j - 1536)];
        else                v = W4[(l * NSPEC + s) * 512  + (j - 2560)];
        wsm[t] = v;
    }
    __syncthreads();

    const int aoff1 = d_aoff[1], aoff2 = d_aoff[2], aoff3 = d_aoff[3];
    const int nchunk = d_aoff[NSPEC] / PAD;   // 64-entry warp chunks, bucket-pure

    const int lane = threadIdx.x & 31;
    const int wid  = threadIdx.x >> 5;

    for (int c = blockIdx.x * 4 + wid; c < nchunk; c += gridDim.x * 4) {
        const int pbase = c * PAD;
        // species uniform across the whole 64-entry chunk (buckets 64-aligned)
        const int sp = (pbase >= aoff2) ? ((pbase >= aoff3) ? 3 : 2)
                                        : ((pbase >= aoff1) ? 1 : 0);
        const float* w = &wsm[sp * SPBLK];

        const int idx0 = d_sorted[pbase + lane];
        const int idx1 = d_sorted[pbase + lane + 32];

        float a0[HID], b0[HID], a1[HID], b1[HID];

        const float4* x0 = reinterpret_cast<const float4*>(xg + ((size_t)idx0 * LMAX + l) * NM);
        const float4* x1 = reinterpret_cast<const float4*>(xg + ((size_t)idx1 * LMAX + l) * NM);
#pragma unroll
        for (int q = 0; q < 4; ++q) {
            float4 v0 = x0[q], v1 = x1[q];
            a0[q * 4 + 0] = v0.x; a0[q * 4 + 1] = v0.y; a0[q * 4 + 2] = v0.z; a0[q * 4 + 3] = v0.w;
            a1[q * 4 + 0] = v1.x; a1[q * 4 + 1] = v1.y; a1[q * 4 + 2] = v1.z; a1[q * 4 + 3] = v1.w;
        }

        layer2d<NM,  HID, true >(w,        a0, a1, b0, b1);   // L1 + silu
        layer2d<HID, HID, true >(w + 512,  b0, b1, a0, a1);   // L2 + silu
        layer2d<HID, HID, true >(w + 1536, a0, a1, b0, b1);   // L3 + silu
        layer2d<HID, NM,  false>(w + 2560, b0, b1, a0, a1);   // L4

        float4* o0 = reinterpret_cast<float4*>(out + ((size_t)idx0 * LMAX + l) * NM);
        float4* o1 = reinterpret_cast<float4*>(out + ((size_t)idx1 * LMAX + l) * NM);
#pragma unroll
        for (int q = 0; q < 4; ++q) {
            o0[q] = make_float4(a0[q * 4 + 0], a0[q * 4 + 1], a0[q * 4 + 2], a0[q * 4 + 3]);
            o1[q] = make_float4(a1[q * 4 + 0], a1[q * 4 + 1], a1[q * 4 + 2], a1[q * 4 + 3]);
        }
    }
}

// ---------------- launch ----------------

extern "C" void kernel_launch(void* const* d_in, const int* in_sizes, int n_in,
                              void* d_out, int out_size) {
    const float* x   = (const float*)d_in[0];
    const int*   sp  = (const int*)d_in[1];   // int32 or int64 — detected on device
    const float* W1  = (const float*)d_in[2];
    const float* W2  = (const float*)d_in[3];
    const float* W3  = (const float*)d_in[4];
    const float* W4  = (const float*)d_in[5];
    float*       out = (float*)d_out;

    const int nblk = (N_PAIRS + 255) / 256;

    k_init<<<1, 256>>>(sp);
    k_hist<<<nblk, 256>>>(sp);
    k_offsets<<<1, 1>>>();
    k_scatter<<<nblk, 256>>>(sp);
    k_pad<<<NSPEC, PAD>>>();

    // ~3 CTAs per SM resident, one wave: 444 x 4(l) CTAs, 4 warps each
    dim3 grid(444, LMAX);
    k_mlp<<<grid, 128>>>(x, W1, W2, W3, W4, out);
}